// round 12
// baseline (speedup 1.0000x reference)
#include <cuda_runtime.h>
#include <cuda_bf16.h>
#include <cstdint>

#define B_  8
#define C_  64
#define H_  128
#define W_  128
#define OC_ 128
#define HP_ 130

#define NSM 152
#define ROWB 16640                    // one padded row slab: 130 px * 64 ch * 2 B
#define TAPB 16384                    // one tap of W
#define SE_OFF   (9 * TAPB)           // 147456: E ring (4 slabs)
#define PART_OFF (SE_OFF + 4 * ROWB)  // 214016: partial-sum ring 4 x [2][132] f32
#define RZ_OFF   (PART_OFF + 4224)    // 218240: rz (128 floats)
#define CONV_SMEM (RZ_OFF + 512)      // 218752

// ---------------------------------------------------------------------------
__device__ __forceinline__ uint32_t smem_u32(const void* p) {
    uint32_t a;
    asm("{ .reg .u64 t; cvta.to.shared.u64 t, %1; cvt.u32.u64 %0, t; }" : "=r"(a) : "l"(p));
    return a;
}
#define LDSM_X4(r0, r1, r2, r3, addr) \
    asm volatile("ldmatrix.sync.aligned.m8n8.x4.shared.b16 {%0,%1,%2,%3}, [%4];" \
        : "=r"(r0), "=r"(r1), "=r"(r2), "=r"(r3) : "r"(addr))

__device__ __forceinline__ void mma16816(float* c, const uint32_t* a,
                                         uint32_t b0, uint32_t b1) {
    asm volatile(
        "mma.sync.aligned.m16n8k16.row.col.f32.bf16.bf16.f32 "
        "{%0,%1,%2,%3}, {%4,%5,%6,%7}, {%8,%9}, {%0,%1,%2,%3};"
        : "+f"(c[0]), "+f"(c[1]), "+f"(c[2]), "+f"(c[3])
        : "r"(a[0]), "r"(a[1]), "r"(a[2]), "r"(a[3]), "r"(b0), "r"(b1));
}

// ---------------------------------------------------------------------------
// Single fused persistent kernel.
//  - W: rearranged in-CTA from `memory` into resident swizzled smem (9 taps).
//  - E: exp(x) computed straight into a 4-slot smem slab ring (never in DRAM).
//  - MMA loop identical to R9 (warp tile 64oc x 32px, 8 warps, 2 syncs/row).
// ---------------------------------------------------------------------------
__global__ void __launch_bounds__(256) conv_fused_kernel(
    const float* __restrict__ x, const float* __restrict__ mem,
    float* __restrict__ out) {
    extern __shared__ __align__(128) char smem[];
    const uint32_t sbase = smem_u32(smem);
    const int tid = threadIdx.x;
    const int wid = tid >> 5, lane = tid & 31;
    const int wm = wid & 1, wn = wid >> 1;     // 2 x 4 warp grid

    const int r0 = (int)(((long)blockIdx.x * (B_ * H_)) / NSM);
    const int r1 = (int)(((long)(blockIdx.x + 1) * (B_ * H_)) / NSM);

    float* Pring = reinterpret_cast<float*>(smem + PART_OFF);  // [4][2][132]
    float* rzbuf = reinterpret_cast<float*>(smem + RZ_OFF);    // [128]

    // ---- W prep: mem[k][oc] (k = c*9 + tap) -> Wsm[tap][oc][c] bf16 swizzled
    {
        const float4* m4 = reinterpret_cast<const float4*>(mem);
#pragma unroll 1
        for (int base = 0; base < 18432; base += 2048) {
            float4 v[8];
#pragma unroll
            for (int u = 0; u < 8; u++) v[u] = m4[base + u * 256 + tid];
#pragma unroll
            for (int u = 0; u < 8; u++) {
                int i  = base + u * 256 + tid;
                int k  = i >> 5;
                int oc0 = (i & 31) * 4;
                int c  = k / 9, tap = k - 9 * c;
                char* tb = smem + tap * TAPB;
                float vv[4] = {v[u].x, v[u].y, v[u].z, v[u].w};
#pragma unroll
                for (int q = 0; q < 4; q++) {
                    uint32_t off  = (uint32_t)(oc0 + q) * 128 + c * 2;
                    uint32_t soff = off ^ ((off >> 3) & 0x70);
                    *reinterpret_cast<__nv_bfloat16*>(tb + soff) =
                        __float2bfloat16(vv[q]);
                }
            }
        }
    }

    // ---- E slab producer: exp(x row) -> swizzled ring slot + channel partials
    auto produce = [&](int bb, int hp) {
        const int slot = hp & 3;
        char* sl = smem + SE_OFF + slot * ROWB;
        float* P = Pring + slot * 264;                 // [2][132]
        if (hp == 0 || hp == HP_ - 1) {
            for (int i = tid; i < ROWB / 4; i += 256)
                reinterpret_cast<uint32_t*>(sl)[i] = 0x3F803F80u;  // bf16 1.0 x2
            for (int i = tid; i < 260; i += 256) {
                int half = i / 130, wp = i - half * 130;
                P[half * 132 + wp] = 32.f;
            }
        } else {
            const int w = tid & 127, half = tid >> 7;
            const float* xp = x + (((size_t)(bb * C_ + half * 32) * H_) +
                                   (hp - 1)) * W_ + w;
            float s = 0.f;
#pragma unroll
            for (int cc = 0; cc < 32; cc++) {
                float e = __expf(xp[(size_t)cc * H_ * W_]);
                s += e;
                int c = half * 32 + cc;
                uint32_t off  = (uint32_t)(1 + w) * 128 + c * 2;
                uint32_t soff = off ^ ((off >> 3) & 0x70);
                *reinterpret_cast<__nv_bfloat16*>(sl + soff) = __float2bfloat16(e);
            }
            P[half * 132 + 1 + w] = s;
            if (tid < 128) {   // padded-w border pixels (wp=0, 129) = 1.0
                int c = tid & 63, wsel = tid >> 6;
                uint32_t off  = (uint32_t)(wsel ? 129 * 128 : 0) + c * 2;
                uint32_t soff = off ^ ((off >> 3) & 0x70);
                *reinterpret_cast<__nv_bfloat16*>(sl + soff) = __float2bfloat16(1.0f);
            }
            if (tid < 4)
                P[(tid >> 1) * 132 + ((tid & 1) ? 129 : 0)] = 32.f;
        }
    };

    // ---- per-warp ldmatrix addressing constants (R9) ----
    int aRow[4], aSw[4];
#pragma unroll
    for (int mi = 0; mi < 4; mi++) {
        int row = wm * 64 + mi * 16 + (lane & 15);
        aRow[mi] = row * 128;
        aSw[mi]  = (row & 7) * 16;
    }
    const int aCol = (lane >> 4) << 4;
    int bRowBase[2];
#pragma unroll
    for (int nb = 0; nb < 2; nb++)
        bRowBase[nb] = wn * 32 + nb * 16 + ((lane >> 4) << 3) + (lane & 7);
    const int bCol = ((lane >> 3) & 1) << 4;
    const int ocB  = wm * 64 + (lane >> 2);
    const int wB   = wn * 32 + (lane & 3) * 2;

    int r = r0;
#pragma unroll 1
    while (r < r1) {
        const int bb = r >> 7;
        const int seg_end = min(r1, (bb + 1) << 7);

        {   // bootstrap: first 3 slabs of this segment
            const int h0 = r & 127;
            produce(bb, h0);
            produce(bb, h0 + 1);
            produce(bb, h0 + 2);
        }

#pragma unroll 1
        for (int i = r; i < seg_end; i++) {
            const int h = i & 127;
            __syncthreads();                               // (1) produce visible

            if (tid < 128) {                               // (2) rz from partials
                float s = 0.f;
#pragma unroll
                for (int ii = 0; ii < 3; ii++) {
                    const float* P = Pring + ((h + ii) & 3) * 264;
#pragma unroll
                    for (int j = 0; j < 3; j++)
                        s += P[tid + j] + P[132 + tid + j];
                }
                rzbuf[tid] = 1.0f / s;
            }

            float acc[4][4][4];
#pragma unroll
            for (int a0 = 0; a0 < 4; a0++)
#pragma unroll
                for (int a1 = 0; a1 < 4; a1++)
#pragma unroll
                    for (int a2 = 0; a2 < 4; a2++) acc[a0][a1][a2] = 0.f;

#pragma unroll
            for (int t = 0; t < 9; t++) {                  // (3) MMA
                const int kh = t / 3, kw = t - 3 * kh;
                const uint32_t sA = sbase + t * TAPB;
                const uint32_t sE = sbase + SE_OFF + ((h + kh) & 3) * ROWB;
#pragma unroll
                for (int ks = 0; ks < 4; ks++) {
                    uint32_t af[4][4];
#pragma unroll
                    for (int mi = 0; mi < 4; mi++) {
                        uint32_t addr = sA + aRow[mi] + ((ks * 32 + aCol) ^ aSw[mi]);
                        LDSM_X4(af[mi][0], af[mi][1], af[mi][2], af[mi][3], addr);
                    }
                    uint32_t bf[2][4];
#pragma unroll
                    for (int nb = 0; nb < 2; nb++) {
                        int row = bRowBase[nb] + kw;
                        uint32_t addr = sE + row * 128 +
                                        ((ks * 32 + bCol) ^ ((row & 7) * 16));
                        LDSM_X4(bf[nb][0], bf[nb][1], bf[nb][2], bf[nb][3], addr);
                    }
#pragma unroll
                    for (int mi = 0; mi < 4; mi++)
#pragma unroll
                        for (int ni = 0; ni < 4; ni++) {
                            uint32_t b0 = bf[ni >> 1][(ni & 1) * 2];
                            uint32_t b1 = bf[ni >> 1][(ni & 1) * 2 + 1];
                            mma16816(acc[mi][ni], af[mi], b0, b1);
                        }
                }
            }
            __syncthreads();                               // (4) MMA done, rz visible

            if (i + 1 < seg_end) produce(bb, h + 3);       // (5) next slab

            // (6) epilogue: scale + store
#pragma unroll
            for (int mi = 0; mi < 4; mi++)
#pragma unroll
                for (int ni = 0; ni < 4; ni++) {
                    int oc = ocB + mi * 16;
                    int w  = wB + ni * 8;
                    float z0 = rzbuf[w], z1 = rzbuf[w + 1];
                    float* p0 = out + (((size_t)bb * OC_ + oc) * H_ + h) * W_ + w;
                    float2 v0 = make_float2(acc[mi][ni][0] * z0, acc[mi][ni][1] * z1);
                    float2 v1 = make_float2(acc[mi][ni][2] * z0, acc[mi][ni][3] * z1);
                    *reinterpret_cast<float2*>(p0) = v0;
                    *reinterpret_cast<float2*>(p0 + (size_t)8 * H_ * W_) = v1;
                }
        }
        r = seg_end;
    }
}

// ---------------------------------------------------------------------------
extern "C" void kernel_launch(void* const* d_in, const int* in_sizes, int n_in,
                              void* d_out, int out_size) {
    const float* x   = (const float*)d_in[0];   // [8,64,128,128]
    const float* mem = (const float*)d_in[1];   // [576,128]
    float* out = (float*)d_out;                 // [8,128,128,128]

    cudaFuncSetAttribute(conv_fused_kernel,
                         cudaFuncAttributeMaxDynamicSharedMemorySize, CONV_SMEM);

    conv_fused_kernel<<<NSM, 256, CONV_SMEM>>>(x, mem, out);
}

// round 13
// speedup vs baseline: 1.0556x; 1.0556x over previous
#include <cuda_runtime.h>
#include <cuda_bf16.h>
#include <cstdint>

#define B_  8
#define C_  64
#define H_  128
#define W_  128
#define OC_ 128
#define HP_ 130

#define NSM 152
#define ROWB 16640                    // one padded row slab: 130 px * 64 ch * 2 B
#define TAPB 16384                    // one tap of W
#define SE_OFF   (9 * TAPB)           // 147456: E ring (4 slabs)
#define PART_OFF (SE_OFF + 4 * ROWB)  // 214016: partial-sum ring 4 x [2][132] f32
#define RZ_OFF   (PART_OFF + 4224)    // 218240: rz (128 floats)
#define CONV_SMEM (RZ_OFF + 512)      // 218752

// ---------------------------------------------------------------------------
__device__ __forceinline__ uint32_t smem_u32(const void* p) {
    uint32_t a;
    asm("{ .reg .u64 t; cvta.to.shared.u64 t, %1; cvt.u32.u64 %0, t; }" : "=r"(a) : "l"(p));
    return a;
}
#define LDSM_X4(r0, r1, r2, r3, addr) \
    asm volatile("ldmatrix.sync.aligned.m8n8.x4.shared.b16 {%0,%1,%2,%3}, [%4];" \
        : "=r"(r0), "=r"(r1), "=r"(r2), "=r"(r3) : "r"(addr))

__device__ __forceinline__ void mma16816(float* c, const uint32_t* a,
                                         uint32_t b0, uint32_t b1) {
    asm volatile(
        "mma.sync.aligned.m16n8k16.row.col.f32.bf16.bf16.f32 "
        "{%0,%1,%2,%3}, {%4,%5,%6,%7}, {%8,%9}, {%0,%1,%2,%3};"
        : "+f"(c[0]), "+f"(c[1]), "+f"(c[2]), "+f"(c[3])
        : "r"(a[0]), "r"(a[1]), "r"(a[2]), "r"(a[3]), "r"(b0), "r"(b1));
}

// ---------------------------------------------------------------------------
// Single fused persistent kernel (R12 fixed):
//  - x prefetched into regs at row top, consumed after the MMA loop
//  - E stores are 4 x STS.128 per thread (phase-floor optimal)
//  - W rearranged in-CTA once; E never touches DRAM
// ---------------------------------------------------------------------------
__global__ void __launch_bounds__(256) conv_fused_kernel(
    const float* __restrict__ x, const float* __restrict__ mem,
    float* __restrict__ out) {
    extern __shared__ __align__(128) char smem[];
    const uint32_t sbase = smem_u32(smem);
    const int tid = threadIdx.x;
    const int wid = tid >> 5, lane = tid & 31;
    const int wm = wid & 1, wn = wid >> 1;     // 2 x 4 warp grid

    const int r0 = (int)(((long)blockIdx.x * (B_ * H_)) / NSM);
    const int r1 = (int)(((long)(blockIdx.x + 1) * (B_ * H_)) / NSM);

    float* Pring = reinterpret_cast<float*>(smem + PART_OFF);  // [4][2][132]
    float* rzbuf = reinterpret_cast<float*>(smem + RZ_OFF);    // [128]

    // ---- W prep: mem[k][oc] (k = c*9 + tap) -> Wsm[tap][oc][c] bf16 swizzled
    {
        const float4* m4 = reinterpret_cast<const float4*>(mem);
#pragma unroll 1
        for (int base = 0; base < 18432; base += 2048) {
            float4 v[8];
#pragma unroll
            for (int u = 0; u < 8; u++) v[u] = m4[base + u * 256 + tid];
#pragma unroll
            for (int u = 0; u < 8; u++) {
                int i  = base + u * 256 + tid;
                int k  = i >> 5;
                int oc0 = (i & 31) * 4;
                int c  = k / 9, tap = k - 9 * c;
                char* tb = smem + tap * TAPB;
                float vv[4] = {v[u].x, v[u].y, v[u].z, v[u].w};
#pragma unroll
                for (int q = 0; q < 4; q++) {
                    uint32_t off  = (uint32_t)(oc0 + q) * 128 + c * 2;
                    uint32_t soff = off ^ ((off >> 3) & 0x70);
                    *reinterpret_cast<__nv_bfloat16*>(tb + soff) =
                        __float2bfloat16(vv[q]);
                }
            }
        }
    }

    const int pw = tid & 127, phalf = tid >> 7;   // producer mapping

    auto load_x = [&](int bb, int hp, float* xa) {
        const float* xp = x + (((size_t)(bb * C_ + phalf * 32) * H_) +
                               (hp - 1)) * W_ + pw;
#pragma unroll
        for (int cc = 0; cc < 32; cc++) xa[cc] = xp[(size_t)cc * H_ * W_];
    };
    auto store_slab = [&](int hp, const float* xa) {
        const int slot = hp & 3;
        char* sl = smem + SE_OFF + slot * ROWB;
        float* P = Pring + slot * 264;
        float s = 0.f;
        uint32_t pk[16];
#pragma unroll
        for (int cc = 0; cc < 32; cc += 2) {
            float e0 = __expf(xa[cc]), e1 = __expf(xa[cc + 1]);
            s += e0 + e1;
            __nv_bfloat162 v = __floats2bfloat162_rn(e0, e1);
            pk[cc >> 1] = *reinterpret_cast<const uint32_t*>(&v);
        }
#pragma unroll
        for (int q = 0; q < 4; q++) {
            uint32_t off  = (uint32_t)(1 + pw) * 128 + (phalf * 32 + q * 8) * 2;
            uint32_t soff = off ^ ((off >> 3) & 0x70);
            *reinterpret_cast<uint4*>(sl + soff) =
                make_uint4(pk[q * 4], pk[q * 4 + 1], pk[q * 4 + 2], pk[q * 4 + 3]);
        }
        P[phalf * 132 + 1 + pw] = s;
        if (tid < 16) {   // padded-w border pixels (wp = 0, 129): all channels 1.0
            int g = tid & 7, wsel = tid >> 3;
            uint32_t off  = (uint32_t)(wsel ? 129 * 128 : 0) + g * 16;
            uint32_t soff = off ^ ((off >> 3) & 0x70);
            *reinterpret_cast<uint4*>(sl + soff) =
                make_uint4(0x3F803F80u, 0x3F803F80u, 0x3F803F80u, 0x3F803F80u);
        }
        if (tid < 4) P[(tid >> 1) * 132 + ((tid & 1) ? 129 : 0)] = 32.f;
    };
    auto store_border = [&](int hp) {   // hp == 0 or HP_-1: whole row = 1.0
        const int slot = hp & 3;
        char* sl = smem + SE_OFF + slot * ROWB;
        float* P = Pring + slot * 264;
        uint4 ones = make_uint4(0x3F803F80u, 0x3F803F80u, 0x3F803F80u, 0x3F803F80u);
        for (int i = tid; i < ROWB / 16; i += 256)
            reinterpret_cast<uint4*>(sl)[i] = ones;
        for (int i = tid; i < 260; i += 256) {
            int half = i / 130, wp = i - half * 130;
            P[half * 132 + wp] = 32.f;
        }
    };

    // ---- per-warp ldmatrix addressing constants ----
    int aRow[4], aSw[4];
#pragma unroll
    for (int mi = 0; mi < 4; mi++) {
        int row = wm * 64 + mi * 16 + (lane & 15);
        aRow[mi] = row * 128;
        aSw[mi]  = (row & 7) * 16;
    }
    const int aCol = (lane >> 4) << 4;
    int bRowBase[2];
#pragma unroll
    for (int nb = 0; nb < 2; nb++)
        bRowBase[nb] = wn * 32 + nb * 16 + ((lane >> 4) << 3) + (lane & 7);
    const int bCol = ((lane >> 3) & 1) << 4;
    const int ocB  = wm * 64 + (lane >> 2);
    const int wB   = wn * 32 + (lane & 3) * 2;

    int r = r0;
#pragma unroll 1
    while (r < r1) {
        const int bb = r >> 7;
        const int seg_end = min(r1, (bb + 1) << 7);

        {   // bootstrap: first 3 slabs of this segment
            const int h0 = r & 127;
#pragma unroll 1
            for (int q = 0; q < 3; q++) {
                int hp = h0 + q;
                if (hp == 0 || hp == HP_ - 1) store_border(hp);
                else { float xa[32]; load_x(bb, hp, xa); store_slab(hp, xa); }
            }
        }

#pragma unroll 1
        for (int i = r; i < seg_end; i++) {
            const int h = i & 127;
            __syncthreads();                               // (1)

            const bool doNext = (i + 1 < seg_end);
            const int hpn = h + 3;
            const bool nInt = doNext && (hpn <= HP_ - 2);
            float xa[32];
            if (nInt) load_x(bb, hpn, xa);                 // prefetch (hidden by MMA)

            if (tid < 128) {                               // rz from partials
                float s = 0.f;
#pragma unroll
                for (int ii = 0; ii < 3; ii++) {
                    const float* P = Pring + ((h + ii) & 3) * 264;
#pragma unroll
                    for (int j = 0; j < 3; j++)
                        s += P[tid + j] + P[132 + tid + j];
                }
                rzbuf[tid] = 1.0f / s;
            }

            float acc[4][4][4];
#pragma unroll
            for (int a0 = 0; a0 < 4; a0++)
#pragma unroll
                for (int a1 = 0; a1 < 4; a1++)
#pragma unroll
                    for (int a2 = 0; a2 < 4; a2++) acc[a0][a1][a2] = 0.f;

#pragma unroll
            for (int t = 0; t < 9; t++) {                  // MMA
                const int kh = t / 3, kw = t - 3 * kh;
                const uint32_t sA = sbase + t * TAPB;
                const uint32_t sE = sbase + SE_OFF + ((h + kh) & 3) * ROWB;
#pragma unroll
                for (int ks = 0; ks < 4; ks++) {
                    uint32_t af[4][4];
#pragma unroll
                    for (int mi = 0; mi < 4; mi++) {
                        uint32_t addr = sA + aRow[mi] + ((ks * 32 + aCol) ^ aSw[mi]);
                        LDSM_X4(af[mi][0], af[mi][1], af[mi][2], af[mi][3], addr);
                    }
                    uint32_t bf[2][4];
#pragma unroll
                    for (int nb = 0; nb < 2; nb++) {
                        int row = bRowBase[nb] + kw;
                        uint32_t addr = sE + row * 128 +
                                        ((ks * 32 + bCol) ^ ((row & 7) * 16));
                        LDSM_X4(bf[nb][0], bf[nb][1], bf[nb][2], bf[nb][3], addr);
                    }
#pragma unroll
                    for (int mi = 0; mi < 4; mi++)
#pragma unroll
                        for (int ni = 0; ni < 4; ni++) {
                            uint32_t b0 = bf[ni >> 1][(ni & 1) * 2];
                            uint32_t b1 = bf[ni >> 1][(ni & 1) * 2 + 1];
                            mma16816(acc[mi][ni], af[mi], b0, b1);
                        }
                }
            }

            // produce next slab into slot (h+3)&3 == (h-1)&3 (unread this row)
            if (nInt) store_slab(hpn, xa);
            else if (doNext) store_border(hpn);

            __syncthreads();                               // (2)

            // epilogue: scale + store
#pragma unroll
            for (int mi = 0; mi < 4; mi++)
#pragma unroll
                for (int ni = 0; ni < 4; ni++) {
                    int oc = ocB + mi * 16;
                    int w  = wB + ni * 8;
                    float z0 = rzbuf[w], z1 = rzbuf[w + 1];
                    float* p0 = out + (((size_t)bb * OC_ + oc) * H_ + h) * W_ + w;
                    float2 v0 = make_float2(acc[mi][ni][0] * z0, acc[mi][ni][1] * z1);
                    float2 v1 = make_float2(acc[mi][ni][2] * z0, acc[mi][ni][3] * z1);
                    *reinterpret_cast<float2*>(p0) = v0;
                    *reinterpret_cast<float2*>(p0 + (size_t)8 * H_ * W_) = v1;
                }
        }
        r = seg_end;
    }
}

// ---------------------------------------------------------------------------
extern "C" void kernel_launch(void* const* d_in, const int* in_sizes, int n_in,
                              void* d_out, int out_size) {
    const float* x   = (const float*)d_in[0];   // [8,64,128,128]
    const float* mem = (const float*)d_in[1];   // [576,128]
    float* out = (float*)d_out;                 // [8,128,128,128]

    cudaFuncSetAttribute(conv_fused_kernel,
                         cudaFuncAttributeMaxDynamicSharedMemorySize, CONV_SMEM);

    conv_fused_kernel<<<NSM, 256, CONV_SMEM>>>(x, mem, out);
}

// round 14
// speedup vs baseline: 1.0722x; 1.0158x over previous
#include <cuda_runtime.h>
#include <cuda_bf16.h>
#include <cstdint>

#define B_  8
#define C_  64
#define H_  128
#define W_  128
#define OC_ 128
#define HP_ 130

#define NSM 152
#define ROWB 16640                    // one padded row slab: 130 px * 64 ch * 2 B
#define TAPB 16384                    // one tap of W
#define SE_OFF   (9 * TAPB)           // 147456: E ring (4 slabs)
#define PART_OFF (SE_OFF + 4 * ROWB)  // 214016: partial-sum ring 4 x [2][132] f32
#define RZ_OFF   (PART_OFF + 4224)    // 218240: rz (128 floats)
#define CONV_SMEM (RZ_OFF + 512)      // 218752

// ---------------------------------------------------------------------------
__device__ __forceinline__ uint32_t smem_u32(const void* p) {
    uint32_t a;
    asm("{ .reg .u64 t; cvta.to.shared.u64 t, %1; cvt.u32.u64 %0, t; }" : "=r"(a) : "l"(p));
    return a;
}
#define LDSM_X4(r0, r1, r2, r3, addr) \
    asm volatile("ldmatrix.sync.aligned.m8n8.x4.shared.b16 {%0,%1,%2,%3}, [%4];" \
        : "=r"(r0), "=r"(r1), "=r"(r2), "=r"(r3) : "r"(addr))

__device__ __forceinline__ void mma16816(float* c, const uint32_t* a,
                                         uint32_t b0, uint32_t b1) {
    asm volatile(
        "mma.sync.aligned.m16n8k16.row.col.f32.bf16.bf16.f32 "
        "{%0,%1,%2,%3}, {%4,%5,%6,%7}, {%8,%9}, {%0,%1,%2,%3};"
        : "+f"(c[0]), "+f"(c[1]), "+f"(c[2]), "+f"(c[3])
        : "r"(a[0]), "r"(a[1]), "r"(a[2]), "r"(a[3]), "r"(b0), "r"(b1));
}

// ---------------------------------------------------------------------------
// Single fused persistent kernel, staged producer (8-channel chunks):
//  - chunk LDGs issue between taps, consumed 2 taps later (xa[8] live max)
//  - E stores: one STS.128 per chunk (phase-floor optimal)
//  - W rearranged in-CTA once; E never touches DRAM
// ---------------------------------------------------------------------------
__global__ void __launch_bounds__(256) conv_fused_kernel(
    const float* __restrict__ x, const float* __restrict__ mem,
    float* __restrict__ out) {
    extern __shared__ __align__(128) char smem[];
    const uint32_t sbase = smem_u32(smem);
    const int tid = threadIdx.x;
    const int wid = tid >> 5, lane = tid & 31;
    const int wm = wid & 1, wn = wid >> 1;     // 2 x 4 warp grid

    const int r0 = (int)(((long)blockIdx.x * (B_ * H_)) / NSM);
    const int r1 = (int)(((long)(blockIdx.x + 1) * (B_ * H_)) / NSM);

    float* Pring = reinterpret_cast<float*>(smem + PART_OFF);  // [4][2][132]
    float* rzbuf = reinterpret_cast<float*>(smem + RZ_OFF);    // [128]

    // ---- W prep: mem[k][oc] (k = c*9 + tap) -> Wsm[tap][oc][c] bf16 swizzled
    {
        const float4* m4 = reinterpret_cast<const float4*>(mem);
#pragma unroll 1
        for (int base = 0; base < 18432; base += 2048) {
            float4 v[8];
#pragma unroll
            for (int u = 0; u < 8; u++) v[u] = m4[base + u * 256 + tid];
#pragma unroll
            for (int u = 0; u < 8; u++) {
                int i  = base + u * 256 + tid;
                int k  = i >> 5;
                int oc0 = (i & 31) * 4;
                int c  = k / 9, tap = k - 9 * c;
                char* tb = smem + tap * TAPB;
                float vv[4] = {v[u].x, v[u].y, v[u].z, v[u].w};
#pragma unroll
                for (int q = 0; q < 4; q++) {
                    uint32_t off  = (uint32_t)(oc0 + q) * 128 + c * 2;
                    uint32_t soff = off ^ ((off >> 3) & 0x70);
                    *reinterpret_cast<__nv_bfloat16*>(tb + soff) =
                        __float2bfloat16(vv[q]);
                }
            }
        }
    }

    const int pw = tid & 127, phalf = tid >> 7;   // producer mapping

    auto ldg_chunk = [&](int bb, int hp, int q, float* xa) {
        const float* xp = x + (((size_t)(bb * C_ + phalf * 32 + q * 8) * H_) +
                               (hp - 1)) * W_ + pw;
#pragma unroll
        for (int cc = 0; cc < 8; cc++) xa[cc] = xp[(size_t)cc * H_ * W_];
    };
    auto sts_chunk = [&](int hp, int q, const float* xa, float& s) {
        char* sl = smem + SE_OFF + (hp & 3) * ROWB;
        uint32_t pk[4];
#pragma unroll
        for (int cc = 0; cc < 8; cc += 2) {
            float e0 = __expf(xa[cc]), e1 = __expf(xa[cc + 1]);
            s += e0 + e1;
            __nv_bfloat162 v = __floats2bfloat162_rn(e0, e1);
            pk[cc >> 1] = *reinterpret_cast<const uint32_t*>(&v);
        }
        uint32_t off  = (uint32_t)(1 + pw) * 128 + (phalf * 32 + q * 8) * 2;
        uint32_t soff = off ^ ((off >> 3) & 0x70);
        *reinterpret_cast<uint4*>(sl + soff) = make_uint4(pk[0], pk[1], pk[2], pk[3]);
    };
    auto finalize_slab = [&](int hp, float s) {
        const int slot = hp & 3;
        char* sl = smem + SE_OFF + slot * ROWB;
        float* P = Pring + slot * 264;
        P[phalf * 132 + 1 + pw] = s;
        if (tid < 16) {   // padded-w border pixels (wp = 0, 129): all channels 1.0
            int g = tid & 7, wsel = tid >> 3;
            uint32_t off  = (uint32_t)(wsel ? 129 * 128 : 0) + g * 16;
            uint32_t soff = off ^ ((off >> 3) & 0x70);
            *reinterpret_cast<uint4*>(sl + soff) =
                make_uint4(0x3F803F80u, 0x3F803F80u, 0x3F803F80u, 0x3F803F80u);
        }
        if (tid < 4) P[(tid >> 1) * 132 + ((tid & 1) ? 129 : 0)] = 32.f;
    };
    auto store_border = [&](int hp) {   // hp == 0 or HP_-1: whole row = 1.0
        const int slot = hp & 3;
        char* sl = smem + SE_OFF + slot * ROWB;
        float* P = Pring + slot * 264;
        uint4 ones = make_uint4(0x3F803F80u, 0x3F803F80u, 0x3F803F80u, 0x3F803F80u);
        for (int i = tid; i < ROWB / 16; i += 256)
            reinterpret_cast<uint4*>(sl)[i] = ones;
        for (int i = tid; i < 260; i += 256) {
            int half = i / 130, wp = i - half * 130;
            P[half * 132 + wp] = 32.f;
        }
    };

    // ---- per-warp ldmatrix addressing constants ----
    int aRow[4], aSw[4];
#pragma unroll
    for (int mi = 0; mi < 4; mi++) {
        int row = wm * 64 + mi * 16 + (lane & 15);
        aRow[mi] = row * 128;
        aSw[mi]  = (row & 7) * 16;
    }
    const int aCol = (lane >> 4) << 4;
    int bRowBase[2];
#pragma unroll
    for (int nb = 0; nb < 2; nb++)
        bRowBase[nb] = wn * 32 + nb * 16 + ((lane >> 4) << 3) + (lane & 7);
    const int bCol = ((lane >> 3) & 1) << 4;
    const int ocB  = wm * 64 + (lane >> 2);
    const int wB   = wn * 32 + (lane & 3) * 2;

    int r = r0;
#pragma unroll 1
    while (r < r1) {
        const int bb = r >> 7;
        const int seg_end = min(r1, (bb + 1) << 7);

        {   // bootstrap: first 3 slabs of this segment
            const int h0 = r & 127;
#pragma unroll 1
            for (int qq = 0; qq < 3; qq++) {
                int hp = h0 + qq;
                if (hp == 0 || hp == HP_ - 1) store_border(hp);
                else {
                    float s = 0.f;
#pragma unroll 1
                    for (int q = 0; q < 4; q++) {
                        float xa[8];
                        ldg_chunk(bb, hp, q, xa);
                        sts_chunk(hp, q, xa, s);
                    }
                    finalize_slab(hp, s);
                }
            }
        }

#pragma unroll 1
        for (int i = r; i < seg_end; i++) {
            const int h = i & 127;
            __syncthreads();                               // (1)

            const bool doNext = (i + 1 < seg_end);
            const int hpn = h + 3;
            const bool nInt = doNext && (hpn <= HP_ - 2);
            float xa[8];
            float s_acc = 0.f;
            if (nInt) ldg_chunk(bb, hpn, 0, xa);           // chunk 0 in flight

            if (tid < 128) {                               // rz from partials
                float s = 0.f;
#pragma unroll
                for (int ii = 0; ii < 3; ii++) {
                    const float* P = Pring + ((h + ii) & 3) * 264;
#pragma unroll
                    for (int j = 0; j < 3; j++)
                        s += P[tid + j] + P[132 + tid + j];
                }
                rzbuf[tid] = 1.0f / s;
            }

            float acc[4][4][4];
#pragma unroll
            for (int a0 = 0; a0 < 4; a0++)
#pragma unroll
                for (int a1 = 0; a1 < 4; a1++)
#pragma unroll
                    for (int a2 = 0; a2 < 4; a2++) acc[a0][a1][a2] = 0.f;

#pragma unroll
            for (int t = 0; t < 9; t++) {                  // MMA + staged produce
                const int kh = t / 3, kw = t - 3 * kh;
                const uint32_t sA = sbase + t * TAPB;
                const uint32_t sE = sbase + SE_OFF + ((h + kh) & 3) * ROWB;
#pragma unroll
                for (int ks = 0; ks < 4; ks++) {
                    uint32_t af[4][4];
#pragma unroll
                    for (int mi = 0; mi < 4; mi++) {
                        uint32_t addr = sA + aRow[mi] + ((ks * 32 + aCol) ^ aSw[mi]);
                        LDSM_X4(af[mi][0], af[mi][1], af[mi][2], af[mi][3], addr);
                    }
                    uint32_t bf[2][4];
#pragma unroll
                    for (int nb = 0; nb < 2; nb++) {
                        int row = bRowBase[nb] + kw;
                        uint32_t addr = sE + row * 128 +
                                        ((ks * 32 + bCol) ^ ((row & 7) * 16));
                        LDSM_X4(bf[nb][0], bf[nb][1], bf[nb][2], bf[nb][3], addr);
                    }
#pragma unroll
                    for (int mi = 0; mi < 4; mi++)
#pragma unroll
                        for (int ni = 0; ni < 4; ni++) {
                            uint32_t b0 = bf[ni >> 1][(ni & 1) * 2];
                            uint32_t b1 = bf[ni >> 1][(ni & 1) * 2 + 1];
                            mma16816(acc[mi][ni], af[mi], b0, b1);
                        }
                }
                // staged produce at taps 1,3,5,7: consume chunk, issue next
                if ((t & 1) == 1) {
                    const int q = t >> 1;                  // 0..3
                    if (nInt) {
                        sts_chunk(hpn, q, xa, s_acc);
                        if (q < 3) ldg_chunk(bb, hpn, q + 1, xa);
                    } else if (doNext && t == 1) {
                        store_border(hpn);
                    }
                }
            }
            if (nInt) finalize_slab(hpn, s_acc);

            __syncthreads();                               // (2)

            // epilogue: scale + store
#pragma unroll
            for (int mi = 0; mi < 4; mi++)
#pragma unroll
                for (int ni = 0; ni < 4; ni++) {
                    int oc = ocB + mi * 16;
                    int w  = wB + ni * 8;
                    float z0 = rzbuf[w], z1 = rzbuf[w + 1];
                    float* p0 = out + (((size_t)bb * OC_ + oc) * H_ + h) * W_ + w;
                    float2 v0 = make_float2(acc[mi][ni][0] * z0, acc[mi][ni][1] * z1);
                    float2 v1 = make_float2(acc[mi][ni][2] * z0, acc[mi][ni][3] * z1);
                    *reinterpret_cast<float2*>(p0) = v0;
                    *reinterpret_cast<float2*>(p0 + (size_t)8 * H_ * W_) = v1;
                }
        }
        r = seg_end;
    }
}

// ---------------------------------------------------------------------------
extern "C" void kernel_launch(void* const* d_in, const int* in_sizes, int n_in,
                              void* d_out, int out_size) {
    const float* x   = (const float*)d_in[0];   // [8,64,128,128]
    const float* mem = (const float*)d_in[1];   // [576,128]
    float* out = (float*)d_out;                 // [8,128,128,128]

    cudaFuncSetAttribute(conv_fused_kernel,
                         cudaFuncAttributeMaxDynamicSharedMemorySize, CONV_SMEM);

    conv_fused_kernel<<<NSM, 256, CONV_SMEM>>>(x, mem, out);
}